// round 1
// baseline (speedup 1.0000x reference)
#include <cuda_runtime.h>
#include <math.h>

// Problem constants (fixed by the dataset)
#define NN      50000
#define EE_MAX  500000
#define ET_MAX  (NN + EE_MAX)
#define IND     384
#define HID1    1024   // 4 heads * 256
#define C1      256
#define H1      4
#define C2      128
#define NEG_SLOPE 0.2f

// ---------------- scratch (static device globals; no allocation) -------------
static __device__ float g_h0  [(size_t)NN * IND];
static __device__ float g_h1  [(size_t)NN * HID1];
static __device__ float g_agg1[(size_t)NN * HID1];
static __device__ float g_h2  [(size_t)NN * C2];
static __device__ float g_agg2[(size_t)NN * C2];

static __device__ float g_as1[NN * H1];
static __device__ float g_ad1[NN * H1];
static __device__ float g_m1 [NN * H1];
static __device__ float g_dn1[NN * H1];

static __device__ float g_as2[NN];
static __device__ float g_ad2[NN];
static __device__ float g_m2 [NN];
static __device__ float g_dn2[NN];

static __device__ float g_e1[(size_t)ET_MAX * H1];
static __device__ float g_e2[ET_MAX];

static __device__ int g_src[ET_MAX];
static __device__ int g_dst[ET_MAX];
static __device__ int g_is64;

// ---------------- helpers ----------------------------------------------------
__device__ __forceinline__ void atomicMaxF(float* addr, float v) {
    if (v >= 0.f) atomicMax((int*)addr, __float_as_int(v));
    else          atomicMin((unsigned int*)addr, __float_as_uint(v));
}

// ---------------- kernels ----------------------------------------------------

// Detect whether edge_index is int64 or int32 (JAX x64-disabled fallback).
__global__ void k_detect(const void* ei) {
    const unsigned int* u = (const unsigned int*)ei;
    int is64 = 1;
    #pragma unroll
    for (int i = 1; i < 16; i += 2)
        if (u[i] != 0u) is64 = 0;
    g_is64 = is64;
}

// Build int32 src/dst lists with self-loops appended.
__global__ void k_prep(const void* ei, int E, int n) {
    int i = blockIdx.x * blockDim.x + threadIdx.x;
    int tot = E + n;
    if (i >= tot) return;
    int s, d;
    if (i < E) {
        if (g_is64) {
            const long long* p = (const long long*)ei;
            s = (int)p[i]; d = (int)p[E + i];
        } else {
            const int* p = (const int*)ei;
            s = p[i]; d = p[E + i];
        }
    } else {
        s = d = i - E;
    }
    g_src[i] = s; g_dst[i] = d;
}

__global__ void k_fill(float* p, float v, int count) {
    int i = blockIdx.x * blockDim.x + threadIdx.x;
    if (i < count) p[i] = v;
}

// Tiled fp32 SGEMM: C[M,N] = A[M,K] @ B[K,N]; row-major, 128x128x8 tile, 8x8/thread.
// Requires K % 8 == 0 and N % 128 == 0 (true for all three GEMMs here).
__global__ void __launch_bounds__(256) k_sgemm(
    const float* __restrict__ A, const float* __restrict__ B,
    float* __restrict__ C, int M, int N, int K)
{
    __shared__ float As[8][128];
    __shared__ float Bs[8][128];

    int tid = threadIdx.x;
    int row0 = blockIdx.y * 128;
    int col0 = blockIdx.x * 128;

    int arow = tid >> 1;          // 0..127
    int acol = (tid & 1) * 4;     // 0 or 4
    int brow = tid >> 5;          // 0..7
    int bcol = (tid & 31) * 4;    // 0..124
    int trow = (tid >> 4) * 8;
    int tcol = (tid & 15) * 8;

    float acc[8][8];
    #pragma unroll
    for (int i = 0; i < 8; i++)
        #pragma unroll
        for (int j = 0; j < 8; j++) acc[i][j] = 0.f;

    int ar = row0 + arow;
    bool a_ok = (ar < M);
    const float* Ap = A + (size_t)(a_ok ? ar : 0) * K;

    for (int k0 = 0; k0 < K; k0 += 8) {
        #pragma unroll
        for (int i = 0; i < 4; i++) {
            float v = 0.f;
            if (a_ok) v = Ap[k0 + acol + i];
            As[acol + i][arow] = v;
        }
        const float* Bp = B + (size_t)(k0 + brow) * N + col0 + bcol;
        #pragma unroll
        for (int i = 0; i < 4; i++) Bs[brow][bcol + i] = Bp[i];
        __syncthreads();

        #pragma unroll
        for (int kk = 0; kk < 8; kk++) {
            float a[8], b[8];
            #pragma unroll
            for (int i = 0; i < 8; i++) a[i] = As[kk][trow + i];
            #pragma unroll
            for (int j = 0; j < 8; j++) b[j] = Bs[kk][tcol + j];
            #pragma unroll
            for (int i = 0; i < 8; i++)
                #pragma unroll
                for (int j = 0; j < 8; j++) acc[i][j] += a[i] * b[j];
        }
        __syncthreads();
    }

    #pragma unroll
    for (int i = 0; i < 8; i++) {
        int r = row0 + trow + i;
        if (r >= M) break;
        float* Cp = C + (size_t)r * N + col0 + tcol;
        #pragma unroll
        for (int j = 0; j < 8; j++) Cp[j] = acc[i][j];
    }
}

// Encoder epilogue: h0 += node_attr @ enc_W[384:386] + enc_b
__global__ void k_enc_epi(const float* __restrict__ na,
                          const float* __restrict__ encW,
                          const float* __restrict__ encb, int n) {
    int idx = blockIdx.x * blockDim.x + threadIdx.x;
    if (idx >= n * IND) return;
    int node = idx / IND;
    int j = idx - node * IND;
    float v = g_h0[idx];
    v += na[node * 2 + 0] * encW[(size_t)384 * IND + j];
    v += na[node * 2 + 1] * encW[(size_t)385 * IND + j];
    v += encb[j];
    g_h0[idx] = v;
}

// alpha_s / alpha_d for layer 1: one warp per (node, head)
__global__ void k_alpha1(const float* __restrict__ a_src,
                         const float* __restrict__ a_dst, int n) {
    int w = (blockIdx.x * blockDim.x + threadIdx.x) >> 5;
    int lane = threadIdx.x & 31;
    if (w >= n * H1) return;
    int node = w >> 2, head = w & 3;
    const float* hp = g_h1 + (size_t)node * HID1 + head * C1;
    const float* asp = a_src + head * C1;
    const float* adp = a_dst + head * C1;
    float s = 0.f, d = 0.f;
    #pragma unroll
    for (int c = lane; c < C1; c += 32) {
        float v = hp[c];
        s += v * asp[c];
        d += v * adp[c];
    }
    #pragma unroll
    for (int o = 16; o > 0; o >>= 1) {
        s += __shfl_xor_sync(0xffffffffu, s, o);
        d += __shfl_xor_sync(0xffffffffu, d, o);
    }
    if (lane == 0) { g_as1[node * H1 + head] = s; g_ad1[node * H1 + head] = d; }
}

// alpha_s / alpha_d for layer 2: one warp per node
__global__ void k_alpha2(const float* __restrict__ a_src,
                         const float* __restrict__ a_dst, int n) {
    int w = (blockIdx.x * blockDim.x + threadIdx.x) >> 5;
    int lane = threadIdx.x & 31;
    if (w >= n) return;
    const float* hp = g_h2 + (size_t)w * C2;
    float s = 0.f, d = 0.f;
    #pragma unroll
    for (int c = lane; c < C2; c += 32) {
        float v = hp[c];
        s += v * a_src[c];
        d += v * a_dst[c];
    }
    #pragma unroll
    for (int o = 16; o > 0; o >>= 1) {
        s += __shfl_xor_sync(0xffffffffu, s, o);
        d += __shfl_xor_sync(0xffffffffu, d, o);
    }
    if (lane == 0) { g_as2[w] = s; g_ad2[w] = d; }
}

__global__ void k_emax1(int tot) {
    int i = blockIdx.x * blockDim.x + threadIdx.x;
    if (i >= tot) return;
    int s = g_src[i], d = g_dst[i];
    float4 as = *(const float4*)(g_as1 + s * 4);
    float4 ad = *(const float4*)(g_ad1 + d * 4);
    float e[4] = { as.x + ad.x, as.y + ad.y, as.z + ad.z, as.w + ad.w };
    #pragma unroll
    for (int h = 0; h < 4; h++) e[h] = (e[h] >= 0.f) ? e[h] : NEG_SLOPE * e[h];
    *(float4*)(g_e1 + (size_t)i * 4) = make_float4(e[0], e[1], e[2], e[3]);
    #pragma unroll
    for (int h = 0; h < 4; h++) atomicMaxF(&g_m1[d * 4 + h], e[h]);
}

__global__ void k_eexp1(int tot) {
    int i = blockIdx.x * blockDim.x + threadIdx.x;
    if (i >= tot) return;
    int d = g_dst[i];
    float4 e = *(const float4*)(g_e1 + (size_t)i * 4);
    float4 m = *(const float4*)(g_m1 + d * 4);
    float w0 = expf(e.x - m.x), w1 = expf(e.y - m.y);
    float w2 = expf(e.z - m.z), w3 = expf(e.w - m.w);
    *(float4*)(g_e1 + (size_t)i * 4) = make_float4(w0, w1, w2, w3);
    atomicAdd(&g_dn1[d * 4 + 0], w0);
    atomicAdd(&g_dn1[d * 4 + 1], w1);
    atomicAdd(&g_dn1[d * 4 + 2], w2);
    atomicAdd(&g_dn1[d * 4 + 3], w3);
}

// layer-1 aggregation: one 256-thread block per edge; thread t handles
// channel h*256 + t for each head h.
__global__ void __launch_bounds__(256) k_agg1_kernel() {
    __shared__ float sal[4];
    __shared__ int ss, sd;
    int i = blockIdx.x;
    int t = threadIdx.x;
    if (t < 4) {
        int d = g_dst[i];
        sal[t] = g_e1[(size_t)i * 4 + t] / (g_dn1[d * 4 + t] + 1e-16f);
        if (t == 0) { ss = g_src[i]; sd = d; }
    }
    __syncthreads();
    const float* hs = g_h1 + (size_t)ss * HID1;
    float* od = g_agg1 + (size_t)sd * HID1;
    #pragma unroll
    for (int h = 0; h < 4; h++) {
        int c = h * C1 + t;
        atomicAdd(&od[c], hs[c] * sal[h]);
    }
}

// bias + ELU, overwriting g_h1 with layer-1 output features
__global__ void k_post1(const float* __restrict__ b1, int n) {
    int idx = blockIdx.x * blockDim.x + threadIdx.x;
    if (idx >= n * HID1) return;
    int j = idx & (HID1 - 1);
    float v = g_agg1[idx] + b1[j];
    g_h1[idx] = (v > 0.f) ? v : expm1f(v);
}

__global__ void k_emax2(int tot) {
    int i = blockIdx.x * blockDim.x + threadIdx.x;
    if (i >= tot) return;
    int s = g_src[i], d = g_dst[i];
    float e = g_as2[s] + g_ad2[d];
    e = (e >= 0.f) ? e : NEG_SLOPE * e;
    g_e2[i] = e;
    atomicMaxF(&g_m2[d], e);
}

__global__ void k_eexp2(int tot) {
    int i = blockIdx.x * blockDim.x + threadIdx.x;
    if (i >= tot) return;
    int d = g_dst[i];
    float w = expf(g_e2[i] - g_m2[d]);
    g_e2[i] = w;
    atomicAdd(&g_dn2[d], w);
}

// layer-2 aggregation: one 128-thread block per edge
__global__ void __launch_bounds__(128) k_agg2_kernel() {
    __shared__ float sal;
    __shared__ int ss, sd;
    int i = blockIdx.x;
    int t = threadIdx.x;
    if (t == 0) {
        int d = g_dst[i];
        sal = g_e2[i] / (g_dn2[d] + 1e-16f);
        ss = g_src[i]; sd = d;
    }
    __syncthreads();
    atomicAdd(&g_agg2[(size_t)sd * C2 + t], g_h2[(size_t)ss * C2 + t] * sal);
}

__global__ void k_final(const float* __restrict__ b2, float* __restrict__ out, int n) {
    int idx = blockIdx.x * blockDim.x + threadIdx.x;
    if (idx >= n * C2) return;
    out[idx] = g_agg2[idx] + b2[idx & (C2 - 1)];
}

// ---------------- host launcher ----------------------------------------------
extern "C" void kernel_launch(void* const* d_in, const int* in_sizes, int n_in,
                              void* d_out, int out_size) {
    const float* x       = (const float*)d_in[0];
    const float* na      = (const float*)d_in[1];
    const void*  ei      = d_in[2];
    const float* encW    = (const float*)d_in[3];
    const float* encb    = (const float*)d_in[4];
    const float* W1      = (const float*)d_in[5];
    const float* a_src1  = (const float*)d_in[6];
    const float* a_dst1  = (const float*)d_in[7];
    const float* b1      = (const float*)d_in[8];
    const float* W2      = (const float*)d_in[9];
    const float* a_src2  = (const float*)d_in[10];
    const float* a_dst2  = (const float*)d_in[11];
    const float* b2      = (const float*)d_in[12];
    float* out = (float*)d_out;

    int n = in_sizes[0] / IND;
    int E = in_sizes[2] / 2;
    int tot = E + n;

    // device pointers to __device__ globals (for fill kernels)
    float *p_agg1, *p_agg2, *p_m1, *p_m2, *p_dn1, *p_dn2;
    cudaGetSymbolAddress((void**)&p_agg1, g_agg1);
    cudaGetSymbolAddress((void**)&p_agg2, g_agg2);
    cudaGetSymbolAddress((void**)&p_m1,  g_m1);
    cudaGetSymbolAddress((void**)&p_m2,  g_m2);
    cudaGetSymbolAddress((void**)&p_dn1, g_dn1);
    cudaGetSymbolAddress((void**)&p_dn2, g_dn2);

    const float NEG_INF = -__builtin_huge_valf();

    // edge prep
    k_detect<<<1, 1>>>(ei);
    k_prep<<<(tot + 255) / 256, 256>>>(ei, E, n);

    // init
    k_fill<<<(n * HID1 + 255) / 256, 256>>>(p_agg1, 0.f, n * HID1);
    k_fill<<<(n * C2 + 255) / 256, 256>>>(p_agg2, 0.f, n * C2);
    k_fill<<<(n * H1 + 255) / 256, 256>>>(p_m1, NEG_INF, n * H1);
    k_fill<<<(n * H1 + 255) / 256, 256>>>(p_dn1, 0.f, n * H1);
    k_fill<<<(n + 255) / 256, 256>>>(p_m2, NEG_INF, n);
    k_fill<<<(n + 255) / 256, 256>>>(p_dn2, 0.f, n);

    float *p_h0, *p_h1, *p_h2;
    cudaGetSymbolAddress((void**)&p_h0, g_h0);
    cudaGetSymbolAddress((void**)&p_h1, g_h1);
    cudaGetSymbolAddress((void**)&p_h2, g_h2);

    // encoder: h0 = x @ encW[0:384] ; += node_attr part + bias
    {
        dim3 grid(IND / 128, (n + 127) / 128);
        k_sgemm<<<grid, 256>>>(x, encW, p_h0, n, IND, IND);
        k_enc_epi<<<(n * IND + 255) / 256, 256>>>(na, encW, encb, n);
    }

    // GAT layer 1
    {
        dim3 grid(HID1 / 128, (n + 127) / 128);
        k_sgemm<<<grid, 256>>>(p_h0, W1, p_h1, n, HID1, IND);
    }
    k_alpha1<<<((n * H1 * 32) + 127) / 128, 128>>>(a_src1, a_dst1, n);
    k_emax1<<<(tot + 255) / 256, 256>>>(tot);
    k_eexp1<<<(tot + 255) / 256, 256>>>(tot);
    k_agg1_kernel<<<tot, 256>>>();
    k_post1<<<(n * HID1 + 255) / 256, 256>>>(b1, n);

    // GAT layer 2
    {
        dim3 grid(C2 / 128, (n + 127) / 128);
        k_sgemm<<<grid, 256>>>(p_h1, W2, p_h2, n, C2, HID1);
    }
    k_alpha2<<<((n * 32) + 127) / 128, 128>>>(a_src2, a_dst2, n);
    k_emax2<<<(tot + 255) / 256, 256>>>(tot);
    k_eexp2<<<(tot + 255) / 256, 256>>>(tot);
    k_agg2_kernel<<<tot, 128>>>();
    k_final<<<(n * C2 + 255) / 256, 256>>>(b2, out, n);
}

// round 2
// speedup vs baseline: 1.9941x; 1.9941x over previous
#include <cuda_runtime.h>
#include <math.h>

// Problem constants (fixed by the dataset)
#define NN      50000
#define EE_MAX  500000
#define ET_MAX  (NN + EE_MAX)
#define IND     384
#define HID1    1024   // 4 heads * 256
#define C1      256
#define H1      4
#define C2      128
#define NEG_SLOPE 0.2f

// ---------------- scratch (static device globals; no allocation) -------------
static __device__ __align__(16) float g_h0  [(size_t)NN * IND];
static __device__ __align__(16) float g_h1  [(size_t)NN * HID1];
static __device__ __align__(16) float g_o1  [(size_t)NN * HID1];  // layer-1 output (post ELU)
static __device__ __align__(16) float g_h2  [(size_t)NN * C2];

static __device__ __align__(16) float g_as1[NN * H1];
static __device__ __align__(16) float g_ad1[NN * H1];
static __device__ float g_as2[NN];
static __device__ float g_ad2[NN];

static __device__ __align__(16) float g_w1[(size_t)ET_MAX * H1];
static __device__ float g_w2[ET_MAX];

static __device__ int g_src[ET_MAX];
static __device__ int g_dst[ET_MAX];
static __device__ int g_deg[NN];
static __device__ int g_cursor[NN];
static __device__ int g_rowstart[NN + 1];
static __device__ int g_csr_src[ET_MAX];
static __device__ int g_is64;

// ---------------- kernels ----------------------------------------------------

// Detect whether edge_index is int64 or int32 (JAX x64-disabled fallback).
__global__ void k_detect(const void* ei) {
    const unsigned int* u = (const unsigned int*)ei;
    int is64 = 1;
    #pragma unroll
    for (int i = 1; i < 16; i += 2)
        if (u[i] != 0u) is64 = 0;
    g_is64 = is64;
}

// Build int32 src/dst lists with self-loops appended.
__global__ void k_prep(const void* ei, int E, int n) {
    int i = blockIdx.x * blockDim.x + threadIdx.x;
    int tot = E + n;
    if (i >= tot) return;
    int s, d;
    if (i < E) {
        if (g_is64) {
            const long long* p = (const long long*)ei;
            s = (int)p[i]; d = (int)p[E + i];
        } else {
            const int* p = (const int*)ei;
            s = p[i]; d = p[E + i];
        }
    } else {
        s = d = i - E;
    }
    g_src[i] = s; g_dst[i] = d;
}

__global__ void k_filli(int* p, int v, int count) {
    int i = blockIdx.x * blockDim.x + threadIdx.x;
    if (i < count) p[i] = v;
}

__global__ void k_hist(int tot) {
    int i = blockIdx.x * blockDim.x + threadIdx.x;
    if (i < tot) atomicAdd(&g_deg[g_dst[i]], 1);
}

// Single-block exclusive scan over g_deg -> g_rowstart (n <= 1024*49)
__global__ void __launch_bounds__(1024) k_scan(int n) {
    __shared__ int s_sum[1024];
    int t = threadIdx.x;
    const int CH = (NN + 1023) / 1024;   // 49
    int base = t * CH;
    int sum = 0;
    for (int i = 0; i < CH; i++) {
        int idx = base + i;
        if (idx < n) sum += g_deg[idx];
    }
    s_sum[t] = sum;
    __syncthreads();
    for (int o = 1; o < 1024; o <<= 1) {
        int v = 0;
        if (t >= o) v = s_sum[t - o];
        __syncthreads();
        if (t >= o) s_sum[t] += v;
        __syncthreads();
    }
    int run = (t > 0) ? s_sum[t - 1] : 0;
    for (int i = 0; i < CH; i++) {
        int idx = base + i;
        if (idx < n) { g_rowstart[idx] = run; run += g_deg[idx]; }
    }
    if (t == 1023) g_rowstart[n] = s_sum[1023];
}

__global__ void k_scatter(int tot) {
    int i = blockIdx.x * blockDim.x + threadIdx.x;
    if (i >= tot) return;
    int d = g_dst[i];
    int pos = atomicAdd(&g_cursor[d], 1);
    g_csr_src[g_rowstart[d] + pos] = g_src[i];
}

// Tiled fp32 SGEMM: C[M,N] = A[M,K] @ B[K,N]; row-major, 128x128x8 tile, 8x8/thread.
// Requires K % 8 == 0, N % 128 == 0, A/B/C 16B-aligned, K*4 % 16 == 0.
__global__ void __launch_bounds__(256) k_sgemm(
    const float* __restrict__ A, const float* __restrict__ B,
    float* __restrict__ C, int M, int N, int K)
{
    __shared__ __align__(16) float As[8][128];
    __shared__ __align__(16) float Bs[8][128];

    int tid = threadIdx.x;
    int row0 = blockIdx.y * 128;
    int col0 = blockIdx.x * 128;

    int arow = tid >> 1;          // 0..127
    int acol = (tid & 1) * 4;     // 0 or 4
    int brow = tid >> 5;          // 0..7
    int bcol = (tid & 31) * 4;    // 0..124
    int trow = (tid >> 4) * 8;
    int tcol = (tid & 15) * 8;

    float acc[8][8];
    #pragma unroll
    for (int i = 0; i < 8; i++)
        #pragma unroll
        for (int j = 0; j < 8; j++) acc[i][j] = 0.f;

    int ar = row0 + arow;
    bool a_ok = (ar < M);
    const float* Ap = A + (size_t)(a_ok ? ar : 0) * K;

    for (int k0 = 0; k0 < K; k0 += 8) {
        float4 av = make_float4(0.f, 0.f, 0.f, 0.f);
        if (a_ok) av = *(const float4*)(Ap + k0 + acol);
        As[acol + 0][arow] = av.x;
        As[acol + 1][arow] = av.y;
        As[acol + 2][arow] = av.z;
        As[acol + 3][arow] = av.w;
        const float* Bp = B + (size_t)(k0 + brow) * N + col0 + bcol;
        *(float4*)&Bs[brow][bcol] = *(const float4*)Bp;
        __syncthreads();

        #pragma unroll
        for (int kk = 0; kk < 8; kk++) {
            float4 a0 = *(const float4*)&As[kk][trow];
            float4 a1 = *(const float4*)&As[kk][trow + 4];
            float4 b0 = *(const float4*)&Bs[kk][tcol];
            float4 b1 = *(const float4*)&Bs[kk][tcol + 4];
            float a[8] = {a0.x, a0.y, a0.z, a0.w, a1.x, a1.y, a1.z, a1.w};
            float b[8] = {b0.x, b0.y, b0.z, b0.w, b1.x, b1.y, b1.z, b1.w};
            #pragma unroll
            for (int i = 0; i < 8; i++)
                #pragma unroll
                for (int j = 0; j < 8; j++) acc[i][j] += a[i] * b[j];
        }
        __syncthreads();
    }

    #pragma unroll
    for (int i = 0; i < 8; i++) {
        int r = row0 + trow + i;
        if (r >= M) break;
        float* Cp = C + (size_t)r * N + col0 + tcol;
        *(float4*)(Cp)     = make_float4(acc[i][0], acc[i][1], acc[i][2], acc[i][3]);
        *(float4*)(Cp + 4) = make_float4(acc[i][4], acc[i][5], acc[i][6], acc[i][7]);
    }
}

// Encoder epilogue: h0 += node_attr @ enc_W[384:386] + enc_b   (float4)
__global__ void k_enc_epi(const float* __restrict__ na,
                          const float* __restrict__ encW,
                          const float* __restrict__ encb, int n) {
    int idx = blockIdx.x * blockDim.x + threadIdx.x;     // float4 index
    int total = n * (IND / 4);
    if (idx >= total) return;
    int node = idx / (IND / 4);
    int j4 = idx - node * (IND / 4);
    float a0 = na[node * 2 + 0];
    float a1 = na[node * 2 + 1];
    float4 v  = *(float4*)(g_h0 + (size_t)idx * 4);
    float4 w0 = *(const float4*)(encW + (size_t)384 * IND + j4 * 4);
    float4 w1 = *(const float4*)(encW + (size_t)385 * IND + j4 * 4);
    float4 bb = *(const float4*)(encb + j4 * 4);
    v.x += a0 * w0.x + a1 * w1.x + bb.x;
    v.y += a0 * w0.y + a1 * w1.y + bb.y;
    v.z += a0 * w0.z + a1 * w1.z + bb.z;
    v.w += a0 * w0.w + a1 * w1.w + bb.w;
    *(float4*)(g_h0 + (size_t)idx * 4) = v;
}

// alpha_s / alpha_d for layer 1: one warp per (node, head)
__global__ void k_alpha1(const float* __restrict__ a_src,
                         const float* __restrict__ a_dst, int n) {
    int w = (blockIdx.x * blockDim.x + threadIdx.x) >> 5;
    int lane = threadIdx.x & 31;
    if (w >= n * H1) return;
    int node = w >> 2, head = w & 3;
    const float* hp = g_h1 + (size_t)node * HID1 + head * C1;
    const float* asp = a_src + head * C1;
    const float* adp = a_dst + head * C1;
    float s = 0.f, d = 0.f;
    #pragma unroll
    for (int c = lane; c < C1; c += 32) {
        float v = hp[c];
        s += v * asp[c];
        d += v * adp[c];
    }
    #pragma unroll
    for (int o = 16; o > 0; o >>= 1) {
        s += __shfl_xor_sync(0xffffffffu, s, o);
        d += __shfl_xor_sync(0xffffffffu, d, o);
    }
    if (lane == 0) { g_as1[node * H1 + head] = s; g_ad1[node * H1 + head] = d; }
}

// alpha_s / alpha_d for layer 2: one warp per node
__global__ void k_alpha2(const float* __restrict__ a_src,
                         const float* __restrict__ a_dst, int n) {
    int w = (blockIdx.x * blockDim.x + threadIdx.x) >> 5;
    int lane = threadIdx.x & 31;
    if (w >= n) return;
    const float* hp = g_h2 + (size_t)w * C2;
    float s = 0.f, d = 0.f;
    #pragma unroll
    for (int c = lane; c < C2; c += 32) {
        float v = hp[c];
        s += v * a_src[c];
        d += v * a_dst[c];
    }
    #pragma unroll
    for (int o = 16; o > 0; o >>= 1) {
        s += __shfl_xor_sync(0xffffffffu, s, o);
        d += __shfl_xor_sync(0xffffffffu, d, o);
    }
    if (lane == 0) { g_as2[w] = s; g_ad2[w] = d; }
}

__device__ __forceinline__ float leaky(float e) {
    return (e >= 0.f) ? e : NEG_SLOPE * e;
}

// Fused layer-1 attention softmax + aggregation + bias + ELU.
// One 256-thread block per destination node.
__global__ void __launch_bounds__(256) k_attn_agg1(const float* __restrict__ b1) {
    int d = blockIdx.x;
    int t = threadIdx.x;
    int lane = t & 31;
    int beg = g_rowstart[d];
    int end = g_rowstart[d + 1];
    int deg = end - beg;

    __shared__ float s_inv[4];

    if (t < 32) {  // warp 0: softmax stats
        float4 ad = *(const float4*)(g_ad1 + d * 4);
        float m0 = -INFINITY, m1 = -INFINITY, m2 = -INFINITY, m3 = -INFINITY;
        for (int j = lane; j < deg; j += 32) {
            int s = g_csr_src[beg + j];
            float4 as = *(const float4*)(g_as1 + s * 4);
            float e0 = leaky(as.x + ad.x);
            float e1 = leaky(as.y + ad.y);
            float e2 = leaky(as.z + ad.z);
            float e3 = leaky(as.w + ad.w);
            *(float4*)(g_w1 + (size_t)(beg + j) * 4) = make_float4(e0, e1, e2, e3);
            m0 = fmaxf(m0, e0); m1 = fmaxf(m1, e1);
            m2 = fmaxf(m2, e2); m3 = fmaxf(m3, e3);
        }
        #pragma unroll
        for (int o = 16; o > 0; o >>= 1) {
            m0 = fmaxf(m0, __shfl_xor_sync(0xffffffffu, m0, o));
            m1 = fmaxf(m1, __shfl_xor_sync(0xffffffffu, m1, o));
            m2 = fmaxf(m2, __shfl_xor_sync(0xffffffffu, m2, o));
            m3 = fmaxf(m3, __shfl_xor_sync(0xffffffffu, m3, o));
        }
        float s0 = 0.f, s1 = 0.f, s2 = 0.f, s3 = 0.f;
        for (int j = lane; j < deg; j += 32) {
            float4 e = *(const float4*)(g_w1 + (size_t)(beg + j) * 4);
            float w0 = __expf(e.x - m0), w1 = __expf(e.y - m1);
            float w2 = __expf(e.z - m2), w3 = __expf(e.w - m3);
            *(float4*)(g_w1 + (size_t)(beg + j) * 4) = make_float4(w0, w1, w2, w3);
            s0 += w0; s1 += w1; s2 += w2; s3 += w3;
        }
        #pragma unroll
        for (int o = 16; o > 0; o >>= 1) {
            s0 += __shfl_xor_sync(0xffffffffu, s0, o);
            s1 += __shfl_xor_sync(0xffffffffu, s1, o);
            s2 += __shfl_xor_sync(0xffffffffu, s2, o);
            s3 += __shfl_xor_sync(0xffffffffu, s3, o);
        }
        if (lane == 0) {
            s_inv[0] = 1.f / (s0 + 1e-16f);
            s_inv[1] = 1.f / (s1 + 1e-16f);
            s_inv[2] = 1.f / (s2 + 1e-16f);
            s_inv[3] = 1.f / (s3 + 1e-16f);
        }
    }
    __syncthreads();

    float acc0 = 0.f, acc1 = 0.f, acc2 = 0.f, acc3 = 0.f;
    for (int j = 0; j < deg; j++) {
        int s = g_csr_src[beg + j];
        float4 w = *(const float4*)(g_w1 + (size_t)(beg + j) * 4);
        const float* hs = g_h1 + (size_t)s * HID1;
        acc0 += hs[t]       * w.x;
        acc1 += hs[256 + t] * w.y;
        acc2 += hs[512 + t] * w.z;
        acc3 += hs[768 + t] * w.w;
    }
    float v0 = acc0 * s_inv[0] + b1[t];
    float v1 = acc1 * s_inv[1] + b1[256 + t];
    float v2 = acc2 * s_inv[2] + b1[512 + t];
    float v3 = acc3 * s_inv[3] + b1[768 + t];
    float* od = g_o1 + (size_t)d * HID1;
    od[t]       = (v0 > 0.f) ? v0 : expm1f(v0);
    od[256 + t] = (v1 > 0.f) ? v1 : expm1f(v1);
    od[512 + t] = (v2 > 0.f) ? v2 : expm1f(v2);
    od[768 + t] = (v3 > 0.f) ? v3 : expm1f(v3);
}

// Fused layer-2 attention softmax + aggregation + bias -> out.
// One 128-thread block per destination node.
__global__ void __launch_bounds__(128) k_attn_agg2(const float* __restrict__ b2,
                                                   float* __restrict__ out) {
    int d = blockIdx.x;
    int t = threadIdx.x;
    int lane = t & 31;
    int beg = g_rowstart[d];
    int end = g_rowstart[d + 1];
    int deg = end - beg;

    __shared__ float s_inv;

    if (t < 32) {
        float ad = g_ad2[d];
        float m = -INFINITY;
        for (int j = lane; j < deg; j += 32) {
            int s = g_csr_src[beg + j];
            float e = leaky(g_as2[s] + ad);
            g_w2[beg + j] = e;
            m = fmaxf(m, e);
        }
        #pragma unroll
        for (int o = 16; o > 0; o >>= 1)
            m = fmaxf(m, __shfl_xor_sync(0xffffffffu, m, o));
        float sum = 0.f;
        for (int j = lane; j < deg; j += 32) {
            float w = __expf(g_w2[beg + j] - m);
            g_w2[beg + j] = w;
            sum += w;
        }
        #pragma unroll
        for (int o = 16; o > 0; o >>= 1)
            sum += __shfl_xor_sync(0xffffffffu, sum, o);
        if (lane == 0) s_inv = 1.f / (sum + 1e-16f);
    }
    __syncthreads();

    float acc = 0.f;
    for (int j = 0; j < deg; j++) {
        int s = g_csr_src[beg + j];
        acc += g_h2[(size_t)s * C2 + t] * g_w2[beg + j];
    }
    out[(size_t)d * C2 + t] = acc * s_inv + b2[t];
}

// ---------------- host launcher ----------------------------------------------
extern "C" void kernel_launch(void* const* d_in, const int* in_sizes, int n_in,
                              void* d_out, int out_size) {
    const float* x       = (const float*)d_in[0];
    const void*  ei      = d_in[2];
    const float* na      = (const float*)d_in[1];
    const float* encW    = (const float*)d_in[3];
    const float* encb    = (const float*)d_in[4];
    const float* W1      = (const float*)d_in[5];
    const float* a_src1  = (const float*)d_in[6];
    const float* a_dst1  = (const float*)d_in[7];
    const float* b1      = (const float*)d_in[8];
    const float* W2      = (const float*)d_in[9];
    const float* a_src2  = (const float*)d_in[10];
    const float* a_dst2  = (const float*)d_in[11];
    const float* b2      = (const float*)d_in[12];
    float* out = (float*)d_out;

    int n = in_sizes[0] / IND;
    int E = in_sizes[2] / 2;
    int tot = E + n;

    int *p_deg, *p_cursor;
    cudaGetSymbolAddress((void**)&p_deg, g_deg);
    cudaGetSymbolAddress((void**)&p_cursor, g_cursor);
    float *p_h0, *p_h1, *p_o1, *p_h2;
    cudaGetSymbolAddress((void**)&p_h0, g_h0);
    cudaGetSymbolAddress((void**)&p_h1, g_h1);
    cudaGetSymbolAddress((void**)&p_o1, g_o1);
    cudaGetSymbolAddress((void**)&p_h2, g_h2);

    // ---- CSR build ----
    k_detect<<<1, 1>>>(ei);
    k_prep<<<(tot + 255) / 256, 256>>>(ei, E, n);
    k_filli<<<(n + 255) / 256, 256>>>(p_deg, 0, n);
    k_filli<<<(n + 255) / 256, 256>>>(p_cursor, 0, n);
    k_hist<<<(tot + 255) / 256, 256>>>(tot);
    k_scan<<<1, 1024>>>(n);
    k_scatter<<<(tot + 255) / 256, 256>>>(tot);

    // ---- encoder ----
    {
        dim3 grid(IND / 128, (n + 127) / 128);
        k_sgemm<<<grid, 256>>>(x, encW, p_h0, n, IND, IND);
        k_enc_epi<<<(n * (IND / 4) + 255) / 256, 256>>>(na, encW, encb, n);
    }

    // ---- GAT layer 1 ----
    {
        dim3 grid(HID1 / 128, (n + 127) / 128);
        k_sgemm<<<grid, 256>>>(p_h0, W1, p_h1, n, HID1, IND);
    }
    k_alpha1<<<((n * H1 * 32) + 127) / 128, 128>>>(a_src1, a_dst1, n);
    k_attn_agg1<<<n, 256>>>(b1);

    // ---- GAT layer 2 ----
    {
        dim3 grid(C2 / 128, (n + 127) / 128);
        k_sgemm<<<grid, 256>>>(p_o1, W2, p_h2, n, C2, HID1);
    }
    k_alpha2<<<((n * 32) + 127) / 128, 128>>>(a_src2, a_dst2, n);
    k_attn_agg2<<<n, 128>>>(b2, out);
}

// round 3
// speedup vs baseline: 4.0313x; 2.0216x over previous
#include <cuda_runtime.h>
#include <math.h>
#include <stdint.h>

// Problem constants (fixed by the dataset)
#define NN      50000
#define EE_MAX  500000
#define ET_MAX  (NN + EE_MAX)
#define IND     384
#define HID1    1024   // 4 heads * 256
#define C1      256
#define H1      4
#define C2      128
#define NEG_SLOPE 0.2f

// ---------------- scratch (static device globals; no allocation) -------------
static __device__ __align__(16) float g_h0  [(size_t)NN * IND];
static __device__ __align__(16) float g_h1  [(size_t)NN * HID1];
static __device__ __align__(16) float g_o1  [(size_t)NN * HID1];  // layer-1 output (post ELU)
static __device__ __align__(16) float g_h2  [(size_t)NN * C2];

static __device__ __align__(16) float g_as1[NN * H1];
static __device__ __align__(16) float g_ad1[NN * H1];
static __device__ float g_as2[NN];
static __device__ float g_ad2[NN];

static __device__ __align__(16) float g_w1[(size_t)ET_MAX * H1];
static __device__ float g_w2[ET_MAX];

static __device__ int g_src[ET_MAX];
static __device__ int g_dst[ET_MAX];
static __device__ int g_deg[NN];
static __device__ int g_cursor[NN];
static __device__ int g_rowstart[NN + 1];
static __device__ int g_csr_src[ET_MAX];
static __device__ int g_is64;

// ---------------- mma helpers -------------------------------------------------
__device__ __forceinline__ uint32_t f2tf32(float f) {
    uint32_t u;
    asm("cvt.rna.tf32.f32 %0, %1;" : "=r"(u) : "f"(f));
    return u;
}

__device__ __forceinline__ void mma_tf32(float* c, const uint32_t* a, const uint32_t* b) {
    asm volatile(
        "mma.sync.aligned.m16n8k8.row.col.f32.tf32.tf32.f32 "
        "{%0,%1,%2,%3},{%4,%5,%6,%7},{%8,%9},{%0,%1,%2,%3};"
        : "+f"(c[0]), "+f"(c[1]), "+f"(c[2]), "+f"(c[3])
        : "r"(a[0]), "r"(a[1]), "r"(a[2]), "r"(a[3]), "r"(b[0]), "r"(b[1]));
}

// ---------------- kernels ----------------------------------------------------

// Detect whether edge_index is int64 or int32 (JAX x64-disabled fallback).
__global__ void k_detect(const void* ei) {
    const unsigned int* u = (const unsigned int*)ei;
    int is64 = 1;
    #pragma unroll
    for (int i = 1; i < 16; i += 2)
        if (u[i] != 0u) is64 = 0;
    g_is64 = is64;
}

// Build int32 src/dst lists with self-loops appended.
__global__ void k_prep(const void* ei, int E, int n) {
    int i = blockIdx.x * blockDim.x + threadIdx.x;
    int tot = E + n;
    if (i >= tot) return;
    int s, d;
    if (i < E) {
        if (g_is64) {
            const long long* p = (const long long*)ei;
            s = (int)p[i]; d = (int)p[E + i];
        } else {
            const int* p = (const int*)ei;
            s = p[i]; d = p[E + i];
        }
    } else {
        s = d = i - E;
    }
    g_src[i] = s; g_dst[i] = d;
}

__global__ void k_filli(int* p, int v, int count) {
    int i = blockIdx.x * blockDim.x + threadIdx.x;
    if (i < count) p[i] = v;
}

__global__ void k_hist(int tot) {
    int i = blockIdx.x * blockDim.x + threadIdx.x;
    if (i < tot) atomicAdd(&g_deg[g_dst[i]], 1);
}

// Single-block exclusive scan over g_deg -> g_rowstart
__global__ void __launch_bounds__(1024) k_scan(int n) {
    __shared__ int s_sum[1024];
    int t = threadIdx.x;
    const int CH = (NN + 1023) / 1024;   // 49
    int base = t * CH;
    int sum = 0;
    for (int i = 0; i < CH; i++) {
        int idx = base + i;
        if (idx < n) sum += g_deg[idx];
    }
    s_sum[t] = sum;
    __syncthreads();
    for (int o = 1; o < 1024; o <<= 1) {
        int v = 0;
        if (t >= o) v = s_sum[t - o];
        __syncthreads();
        if (t >= o) s_sum[t] += v;
        __syncthreads();
    }
    int run = (t > 0) ? s_sum[t - 1] : 0;
    for (int i = 0; i < CH; i++) {
        int idx = base + i;
        if (idx < n) { g_rowstart[idx] = run; run += g_deg[idx]; }
    }
    if (t == 1023) g_rowstart[n] = s_sum[1023];
}

__global__ void k_scatter(int tot) {
    int i = blockIdx.x * blockDim.x + threadIdx.x;
    if (i >= tot) return;
    int d = g_dst[i];
    int pos = atomicAdd(&g_cursor[d], 1);
    g_csr_src[g_rowstart[d] + pos] = g_src[i];
}

// ---------------- TF32 tensor-core GEMM ---------------------------------------
// C[M,N] = A[M,K] @ B[K,N], row-major. Requires K%32==0, N%128==0.
// Block: 128x128x32, 256 threads = 8 warps (4x2), warp tile 32x64,
// mma.m16n8k8 tf32, register-prefetch single-buffer pipeline.
__global__ void __launch_bounds__(256, 1) k_mma_gemm(
    const float* __restrict__ A, const float* __restrict__ B,
    float* __restrict__ C, int M, int N, int K)
{
    // As: m-major [128][36] (stride 36 words -> conflict-free frag reads)
    // Bs: k-major [32][136] (stride 136 words -> conflict-free frag reads)
    __shared__ uint32_t As[128][36];
    __shared__ uint32_t Bs[32][136];

    int tid = threadIdx.x;
    int lane = tid & 31;
    int wid = tid >> 5;
    int g = lane >> 2;        // 0..7
    int t = lane & 3;         // 0..3
    int warp_m = wid & 3;     // 0..3 (32 rows each)
    int warp_n = wid >> 2;    // 0..1 (64 cols each)
    int row0 = blockIdx.y * 128;
    int col0 = blockIdx.x * 128;

    float acc[2][8][4];
    #pragma unroll
    for (int mt = 0; mt < 2; mt++)
        #pragma unroll
        for (int nt = 0; nt < 8; nt++)
            #pragma unroll
            for (int i = 0; i < 4; i++) acc[mt][nt][i] = 0.f;

    // gmem load assignments (per thread, 4 float4 each for A and B)
    // A tile: 128 rows x 8 float4;  idx = tid + 256*i : arow = idx>>3, ac4 = idx&7
    // B tile: 32 rows x 32 float4;  idx = tid + 256*i : brow = idx>>5, bc4 = idx&31
    float4 pa[4], pb[4];

    int nIter = K >> 5;

    // prologue: load k-tile 0
    #pragma unroll
    for (int i = 0; i < 4; i++) {
        int idx = tid + 256 * i;
        int ar = idx >> 3, ac4 = idx & 7;
        int gr = row0 + ar;
        pa[i] = (gr < M) ? *(const float4*)(A + (size_t)gr * K + ac4 * 4)
                         : make_float4(0.f, 0.f, 0.f, 0.f);
        int br = idx >> 5, bc4 = idx & 31;
        pb[i] = *(const float4*)(B + (size_t)br * N + col0 + bc4 * 4);
    }
    #pragma unroll
    for (int i = 0; i < 4; i++) {
        int idx = tid + 256 * i;
        int ar = idx >> 3, ac4 = idx & 7;
        uint4 av = make_uint4(f2tf32(pa[i].x), f2tf32(pa[i].y), f2tf32(pa[i].z), f2tf32(pa[i].w));
        *(uint4*)&As[ar][ac4 * 4] = av;
        int br = idx >> 5, bc4 = idx & 31;
        uint4 bv = make_uint4(f2tf32(pb[i].x), f2tf32(pb[i].y), f2tf32(pb[i].z), f2tf32(pb[i].w));
        *(uint4*)&Bs[br][bc4 * 4] = bv;
    }
    __syncthreads();

    for (int it = 0; it < nIter; it++) {
        bool more = (it + 1 < nIter);
        if (more) {
            int k0g = (it + 1) * 32;
            #pragma unroll
            for (int i = 0; i < 4; i++) {
                int idx = tid + 256 * i;
                int ar = idx >> 3, ac4 = idx & 7;
                int gr = row0 + ar;
                pa[i] = (gr < M) ? *(const float4*)(A + (size_t)gr * K + k0g + ac4 * 4)
                                 : make_float4(0.f, 0.f, 0.f, 0.f);
                int br = idx >> 5, bc4 = idx & 31;
                pb[i] = *(const float4*)(B + (size_t)(k0g + br) * N + col0 + bc4 * 4);
            }
        }

        // compute on current smem tile
        #pragma unroll
        for (int kk = 0; kk < 4; kk++) {
            int k0 = kk * 8;
            uint32_t af[2][4];
            #pragma unroll
            for (int mt = 0; mt < 2; mt++) {
                int mb = warp_m * 32 + mt * 16;
                af[mt][0] = As[mb + g][k0 + t];
                af[mt][1] = As[mb + g + 8][k0 + t];
                af[mt][2] = As[mb + g][k0 + t + 4];
                af[mt][3] = As[mb + g + 8][k0 + t + 4];
            }
            #pragma unroll
            for (int nt = 0; nt < 8; nt++) {
                uint32_t bf[2];
                int nb = warp_n * 64 + nt * 8;
                bf[0] = Bs[k0 + t][nb + g];
                bf[1] = Bs[k0 + t + 4][nb + g];
                mma_tf32(acc[0][nt], af[0], bf);
                mma_tf32(acc[1][nt], af[1], bf);
            }
        }

        if (more) {
            __syncthreads();
            #pragma unroll
            for (int i = 0; i < 4; i++) {
                int idx = tid + 256 * i;
                int ar = idx >> 3, ac4 = idx & 7;
                uint4 av = make_uint4(f2tf32(pa[i].x), f2tf32(pa[i].y), f2tf32(pa[i].z), f2tf32(pa[i].w));
                *(uint4*)&As[ar][ac4 * 4] = av;
                int br = idx >> 5, bc4 = idx & 31;
                uint4 bv = make_uint4(f2tf32(pb[i].x), f2tf32(pb[i].y), f2tf32(pb[i].z), f2tf32(pb[i].w));
                *(uint4*)&Bs[br][bc4 * 4] = bv;
            }
            __syncthreads();
        }
    }

    // epilogue
    #pragma unroll
    for (int mt = 0; mt < 2; mt++) {
        int r0 = row0 + warp_m * 32 + mt * 16 + g;
        #pragma unroll
        for (int nt = 0; nt < 8; nt++) {
            int c = col0 + warp_n * 64 + nt * 8 + 2 * t;
            if (r0 < M)
                *(float2*)(C + (size_t)r0 * N + c) = make_float2(acc[mt][nt][0], acc[mt][nt][1]);
            if (r0 + 8 < M)
                *(float2*)(C + (size_t)(r0 + 8) * N + c) = make_float2(acc[mt][nt][2], acc[mt][nt][3]);
        }
    }
}

// Encoder epilogue: h0 += node_attr @ enc_W[384:386] + enc_b   (float4)
__global__ void k_enc_epi(const float* __restrict__ na,
                          const float* __restrict__ encW,
                          const float* __restrict__ encb, int n) {
    int idx = blockIdx.x * blockDim.x + threadIdx.x;     // float4 index
    int total = n * (IND / 4);
    if (idx >= total) return;
    int node = idx / (IND / 4);
    int j4 = idx - node * (IND / 4);
    float a0 = na[node * 2 + 0];
    float a1 = na[node * 2 + 1];
    float4 v  = *(float4*)(g_h0 + (size_t)idx * 4);
    float4 w0 = *(const float4*)(encW + (size_t)384 * IND + j4 * 4);
    float4 w1 = *(const float4*)(encW + (size_t)385 * IND + j4 * 4);
    float4 bb = *(const float4*)(encb + j4 * 4);
    v.x += a0 * w0.x + a1 * w1.x + bb.x;
    v.y += a0 * w0.y + a1 * w1.y + bb.y;
    v.z += a0 * w0.z + a1 * w1.z + bb.z;
    v.w += a0 * w0.w + a1 * w1.w + bb.w;
    *(float4*)(g_h0 + (size_t)idx * 4) = v;
}

// alpha_s / alpha_d for layer 1: one warp per (node, head)
__global__ void k_alpha1(const float* __restrict__ a_src,
                         const float* __restrict__ a_dst, int n) {
    int w = (blockIdx.x * blockDim.x + threadIdx.x) >> 5;
    int lane = threadIdx.x & 31;
    if (w >= n * H1) return;
    int node = w >> 2, head = w & 3;
    const float* hp = g_h1 + (size_t)node * HID1 + head * C1;
    const float* asp = a_src + head * C1;
    const float* adp = a_dst + head * C1;
    float s = 0.f, d = 0.f;
    #pragma unroll
    for (int c = lane; c < C1; c += 32) {
        float v = hp[c];
        s += v * asp[c];
        d += v * adp[c];
    }
    #pragma unroll
    for (int o = 16; o > 0; o >>= 1) {
        s += __shfl_xor_sync(0xffffffffu, s, o);
        d += __shfl_xor_sync(0xffffffffu, d, o);
    }
    if (lane == 0) { g_as1[node * H1 + head] = s; g_ad1[node * H1 + head] = d; }
}

// alpha_s / alpha_d for layer 2: one warp per node
__global__ void k_alpha2(const float* __restrict__ a_src,
                         const float* __restrict__ a_dst, int n) {
    int w = (blockIdx.x * blockDim.x + threadIdx.x) >> 5;
    int lane = threadIdx.x & 31;
    if (w >= n) return;
    const float* hp = g_h2 + (size_t)w * C2;
    float s = 0.f, d = 0.f;
    #pragma unroll
    for (int c = lane; c < C2; c += 32) {
        float v = hp[c];
        s += v * a_src[c];
        d += v * a_dst[c];
    }
    #pragma unroll
    for (int o = 16; o > 0; o >>= 1) {
        s += __shfl_xor_sync(0xffffffffu, s, o);
        d += __shfl_xor_sync(0xffffffffu, d, o);
    }
    if (lane == 0) { g_as2[w] = s; g_ad2[w] = d; }
}

__device__ __forceinline__ float leaky(float e) {
    return (e >= 0.f) ? e : NEG_SLOPE * e;
}

// Fused layer-1 attention softmax + aggregation + bias + ELU.
// One 256-thread block per destination node.
__global__ void __launch_bounds__(256) k_attn_agg1(const float* __restrict__ b1) {
    int d = blockIdx.x;
    int t = threadIdx.x;
    int lane = t & 31;
    int beg = g_rowstart[d];
    int end = g_rowstart[d + 1];
    int deg = end - beg;

    __shared__ float s_inv[4];

    if (t < 32) {  // warp 0: softmax stats
        float4 ad = *(const float4*)(g_ad1 + d * 4);
        float m0 = -INFINITY, m1 = -INFINITY, m2 = -INFINITY, m3 = -INFINITY;
        for (int j = lane; j < deg; j += 32) {
            int s = g_csr_src[beg + j];
            float4 as = *(const float4*)(g_as1 + s * 4);
            float e0 = leaky(as.x + ad.x);
            float e1 = leaky(as.y + ad.y);
            float e2 = leaky(as.z + ad.z);
            float e3 = leaky(as.w + ad.w);
            *(float4*)(g_w1 + (size_t)(beg + j) * 4) = make_float4(e0, e1, e2, e3);
            m0 = fmaxf(m0, e0); m1 = fmaxf(m1, e1);
            m2 = fmaxf(m2, e2); m3 = fmaxf(m3, e3);
        }
        #pragma unroll
        for (int o = 16; o > 0; o >>= 1) {
            m0 = fmaxf(m0, __shfl_xor_sync(0xffffffffu, m0, o));
            m1 = fmaxf(m1, __shfl_xor_sync(0xffffffffu, m1, o));
            m2 = fmaxf(m2, __shfl_xor_sync(0xffffffffu, m2, o));
            m3 = fmaxf(m3, __shfl_xor_sync(0xffffffffu, m3, o));
        }
        float s0 = 0.f, s1 = 0.f, s2 = 0.f, s3 = 0.f;
        for (int j = lane; j < deg; j += 32) {
            float4 e = *(const float4*)(g_w1 + (size_t)(beg + j) * 4);
            float w0 = __expf(e.x - m0), w1 = __expf(e.y - m1);
            float w2 = __expf(e.z - m2), w3 = __expf(e.w - m3);
            *(float4*)(g_w1 + (size_t)(beg + j) * 4) = make_float4(w0, w1, w2, w3);
            s0 += w0; s1 += w1; s2 += w2; s3 += w3;
        }
        #pragma unroll
        for (int o = 16; o > 0; o >>= 1) {
            s0 += __shfl_xor_sync(0xffffffffu, s0, o);
            s1 += __shfl_xor_sync(0xffffffffu, s1, o);
            s2 += __shfl_xor_sync(0xffffffffu, s2, o);
            s3 += __shfl_xor_sync(0xffffffffu, s3, o);
        }
        if (lane == 0) {
            s_inv[0] = 1.f / (s0 + 1e-16f);
            s_inv[1] = 1.f / (s1 + 1e-16f);
            s_inv[2] = 1.f / (s2 + 1e-16f);
            s_inv[3] = 1.f / (s3 + 1e-16f);
        }
    }
    __syncthreads();

    float acc0 = 0.f, acc1 = 0.f, acc2 = 0.f, acc3 = 0.f;
    for (int j = 0; j < deg; j++) {
        int s = g_csr_src[beg + j];
        float4 w = *(const float4*)(g_w1 + (size_t)(beg + j) * 4);
        const float* hs = g_h1 + (size_t)s * HID1;
        acc0 += hs[t]       * w.x;
        acc1 += hs[256 + t] * w.y;
        acc2 += hs[512 + t] * w.z;
        acc3 += hs[768 + t] * w.w;
    }
    float v0 = acc0 * s_inv[0] + b1[t];
    float v1 = acc1 * s_inv[1] + b1[256 + t];
    float v2 = acc2 * s_inv[2] + b1[512 + t];
    float v3 = acc3 * s_inv[3] + b1[768 + t];
    float* od = g_o1 + (size_t)d * HID1;
    od[t]       = (v0 > 0.f) ? v0 : expm1f(v0);
    od[256 + t] = (v1 > 0.f) ? v1 : expm1f(v1);
    od[512 + t] = (v2 > 0.f) ? v2 : expm1f(v2);
    od[768 + t] = (v3 > 0.f) ? v3 : expm1f(v3);
}

// Fused layer-2 attention softmax + aggregation + bias -> out.
// One 128-thread block per destination node.
__global__ void __launch_bounds__(128) k_attn_agg2(const float* __restrict__ b2,
                                                   float* __restrict__ out) {
    int d = blockIdx.x;
    int t = threadIdx.x;
    int lane = t & 31;
    int beg = g_rowstart[d];
    int end = g_rowstart[d + 1];
    int deg = end - beg;

    __shared__ float s_inv;

    if (t < 32) {
        float ad = g_ad2[d];
        float m = -INFINITY;
        for (int j = lane; j < deg; j += 32) {
            int s = g_csr_src[beg + j];
            float e = leaky(g_as2[s] + ad);
            g_w2[beg + j] = e;
            m = fmaxf(m, e);
        }
        #pragma unroll
        for (int o = 16; o > 0; o >>= 1)
            m = fmaxf(m, __shfl_xor_sync(0xffffffffu, m, o));
        float sum = 0.f;
        for (int j = lane; j < deg; j += 32) {
            float w = __expf(g_w2[beg + j] - m);
            g_w2[beg + j] = w;
            sum += w;
        }
        #pragma unroll
        for (int o = 16; o > 0; o >>= 1)
            sum += __shfl_xor_sync(0xffffffffu, sum, o);
        if (lane == 0) s_inv = 1.f / (sum + 1e-16f);
    }
    __syncthreads();

    float acc = 0.f;
    for (int j = 0; j < deg; j++) {
        int s = g_csr_src[beg + j];
        acc += g_h2[(size_t)s * C2 + t] * g_w2[beg + j];
    }
    out[(size_t)d * C2 + t] = acc * s_inv + b2[t];
}

// ---------------- host launcher ----------------------------------------------
extern "C" void kernel_launch(void* const* d_in, const int* in_sizes, int n_in,
                              void* d_out, int out_size) {
    const float* x       = (const float*)d_in[0];
    const float* na      = (const float*)d_in[1];
    const void*  ei      = d_in[2];
    const float* encW    = (const float*)d_in[3];
    const float* encb    = (const float*)d_in[4];
    const float* W1      = (const float*)d_in[5];
    const float* a_src1  = (const float*)d_in[6];
    const float* a_dst1  = (const float*)d_in[7];
    const float* b1      = (const float*)d_in[8];
    const float* W2      = (const float*)d_in[9];
    const float* a_src2  = (const float*)d_in[10];
    const float* a_dst2  = (const float*)d_in[11];
    const float* b2      = (const float*)d_in[12];
    float* out = (float*)d_out;

    int n = in_sizes[0] / IND;
    int E = in_sizes[2] / 2;
    int tot = E + n;

    int *p_deg, *p_cursor;
    cudaGetSymbolAddress((void**)&p_deg, g_deg);
    cudaGetSymbolAddress((void**)&p_cursor, g_cursor);
    float *p_h0, *p_h1, *p_o1, *p_h2;
    cudaGetSymbolAddress((void**)&p_h0, g_h0);
    cudaGetSymbolAddress((void**)&p_h1, g_h1);
    cudaGetSymbolAddress((void**)&p_o1, g_o1);
    cudaGetSymbolAddress((void**)&p_h2, g_h2);

    // ---- CSR build ----
    k_detect<<<1, 1>>>(ei);
    k_prep<<<(tot + 255) / 256, 256>>>(ei, E, n);
    k_filli<<<(n + 255) / 256, 256>>>(p_deg, 0, n);
    k_filli<<<(n + 255) / 256, 256>>>(p_cursor, 0, n);
    k_hist<<<(tot + 255) / 256, 256>>>(tot);
    k_scan<<<1, 1024>>>(n);
    k_scatter<<<(tot + 255) / 256, 256>>>(tot);

    // ---- encoder ----
    {
        dim3 grid(IND / 128, (n + 127) / 128);
        k_mma_gemm<<<grid, 256>>>(x, encW, p_h0, n, IND, IND);
        k_enc_epi<<<(n * (IND / 4) + 255) / 256, 256>>>(na, encW, encb, n);
    }

    // ---- GAT layer 1 ----
    {
        dim3 grid(HID1 / 128, (n + 127) / 128);
        k_mma_gemm<<<grid, 256>>>(p_h0, W1, p_h1, n, HID1, IND);
    }
    k_alpha1<<<((n * H1 * 32) + 127) / 128, 128>>>(a_src1, a_dst1, n);
    k_attn_agg1<<<n, 256>>>(b1);

    // ---- GAT layer 2 ----
    {
        dim3 grid(C2 / 128, (n + 127) / 128);
        k_mma_gemm<<<grid, 256>>>(p_o1, W2, p_h2, n, C2, HID1);
    }
    k_alpha2<<<((n * 32) + 127) / 128, 128>>>(a_src2, a_dst2, n);
    k_attn_agg2<<<n, 128>>>(b2, out);
}